// round 5
// baseline (speedup 1.0000x reference)
#include <cuda_runtime.h>
#include <math.h>
#include <stdint.h>

#define BATCH 16
#define SEQ   512
#define DIM   2048
#define HID   1024
#define NPAIR 128
#define NUN   256
#define ROWS  (BATCH*SEQ)    /* 8192 */
#define MROWS (BATCH*NPAIR)  /* 2048 */

#define NEG_INF (-3.402823466e+38f)

// ---------------- scratch (static device globals; no allocs allowed) ----------
__device__ float g_h[(size_t)ROWS * HID];            // 32 MB  GELU hidden
__device__ float g_imp[ROWS];                        // sigmoid scores
__device__ float g_w[ROWS];                          // clamped normalized importance
__device__ float g_xn[(size_t)ROWS * DIM];           // 64 MB  normalized x
__device__ float g_score[(size_t)BATCH * SEQ * SEQ]; // 16 MB  combined scores
__device__ int   g_pi[BATCH * NPAIR];
__device__ int   g_pj[BATCH * NPAIR];
__device__ int   g_un[BATCH * NUN];
__device__ float g_pair[(size_t)MROWS * 2 * DIM];    // 32 MB  gathered pairs
__device__ float g_hid[(size_t)MROWS * DIM];         // 16 MB  merger hidden

// ---------------- helpers ----------------------------------------------------
__device__ __forceinline__ float gelu_erf(float v) {
    return 0.5f * v * (1.0f + erff(v * 0.70710678118654752440f));
}

// ------- generic 128x128x8 SGEMM body, double-buffered smem pipeline ---------
// Numerics identical to the single-buffer version: same fmaf order per acc.
// mode 0: C[row*N+col] = gelu(acc + bias[col])
// mode 1: out[((row>>7)*384 + (row&127))*DIM + col] = acc + bias[col]  (scatter)
__device__ __forceinline__ void sgemm_body(
    const float* __restrict__ A, const float* __restrict__ B,
    const float* __restrict__ bias, float* __restrict__ C,
    int M, int N, int K, int mode)
{
    __shared__ float As[2][8][128];
    __shared__ float Bs[2][8][128];
    int tid = threadIdx.x;                // 256 threads
    int bx = blockIdx.x, by = blockIdx.y;
    const float* Ab = A + (size_t)(by * 128) * K;
    const float* Bb = B + bx * 128;
    int aRow = tid >> 1, aCol = (tid & 1) * 4;
    int bRow = tid >> 5, bCol = (tid & 31) * 4;
    int ty = tid >> 4,  tx = tid & 15;
    float acc[8][8];
    #pragma unroll
    for (int m = 0; m < 8; m++)
        #pragma unroll
        for (int n = 0; n < 8; n++) acc[m][n] = 0.0f;

    // preload tile 0 into buffer 0
    {
        float4 a4 = *(const float4*)(Ab + (size_t)aRow * K + aCol);
        As[0][aCol + 0][aRow] = a4.x;
        As[0][aCol + 1][aRow] = a4.y;
        As[0][aCol + 2][aRow] = a4.z;
        As[0][aCol + 3][aRow] = a4.w;
        float4 b4 = *(const float4*)(Bb + (size_t)bRow * N + bCol);
        *(float4*)&Bs[0][bRow][bCol] = b4;
    }
    __syncthreads();

    int nk = K >> 3;
    for (int t = 0; t < nk; t++) {
        int cur = t & 1;
        float4 a4n, b4n;
        if (t + 1 < nk) {
            int k0 = (t + 1) << 3;
            a4n = *(const float4*)(Ab + (size_t)aRow * K + k0 + aCol);
            b4n = *(const float4*)(Bb + (size_t)(k0 + bRow) * N + bCol);
        }
        #pragma unroll
        for (int kk = 0; kk < 8; kk++) {
            float af[8], bf[8];
            *(float4*)(af)     = *(const float4*)&As[cur][kk][ty * 8];
            *(float4*)(af + 4) = *(const float4*)&As[cur][kk][ty * 8 + 4];
            *(float4*)(bf)     = *(const float4*)&Bs[cur][kk][tx * 8];
            *(float4*)(bf + 4) = *(const float4*)&Bs[cur][kk][tx * 8 + 4];
            #pragma unroll
            for (int m = 0; m < 8; m++)
                #pragma unroll
                for (int n = 0; n < 8; n++)
                    acc[m][n] = fmaf(af[m], bf[n], acc[m][n]);
        }
        if (t + 1 < nk) {
            int nxt = cur ^ 1;
            As[nxt][aCol + 0][aRow] = a4n.x;
            As[nxt][aCol + 1][aRow] = a4n.y;
            As[nxt][aCol + 2][aRow] = a4n.z;
            As[nxt][aCol + 3][aRow] = a4n.w;
            *(float4*)&Bs[nxt][bRow][bCol] = b4n;
        }
        __syncthreads();
    }

    #pragma unroll
    for (int m = 0; m < 8; m++) {
        int row = by * 128 + ty * 8 + m;
        #pragma unroll
        for (int n4 = 0; n4 < 8; n4 += 4) {
            int col = bx * 128 + tx * 8 + n4;
            float4 v;
            v.x = acc[m][n4 + 0] + bias[col + 0];
            v.y = acc[m][n4 + 1] + bias[col + 1];
            v.z = acc[m][n4 + 2] + bias[col + 2];
            v.w = acc[m][n4 + 3] + bias[col + 3];
            if (mode == 0) {
                v.x = gelu_erf(v.x); v.y = gelu_erf(v.y);
                v.z = gelu_erf(v.z); v.w = gelu_erf(v.w);
                *(float4*)(C + (size_t)row * N + col) = v;
            } else {
                int orow = (row >> 7) * 384 + (row & 127);
                *(float4*)(C + (size_t)orow * DIM + col) = v;
            }
        }
    }
}

__global__ void k_imp_gemm(const float* __restrict__ x,
                           const float* __restrict__ w1,
                           const float* __restrict__ b1) {
    sgemm_body(x, w1, b1, g_h, ROWS, HID, DIM, 0);
}
__global__ void k_mrg_gemm1(const float* __restrict__ w1,
                            const float* __restrict__ b1) {
    sgemm_body(g_pair, w1, b1, g_hid, MROWS, DIM, 2 * DIM, 0);
}
__global__ void k_mrg_gemm2(const float* __restrict__ w2,
                            const float* __restrict__ b2,
                            float* __restrict__ out) {
    sgemm_body(g_hid, w2, b2, out, MROWS, DIM, DIM, 1);
}

// ---------------- importance GEMV + sigmoid (one warp per row) ---------------
__global__ void k_imp(const float* __restrict__ w2, const float* __restrict__ b2) {
    int r = blockIdx.x * 8 + (threadIdx.x >> 5);
    int lane = threadIdx.x & 31;
    const float* hr = g_h + (size_t)r * HID;
    float s = 0.0f;
    for (int c = lane; c < HID; c += 32) s = fmaf(hr[c], w2[c], s);
    #pragma unroll
    for (int o = 16; o; o >>= 1) s += __shfl_down_sync(0xffffffffu, s, o);
    if (lane == 0) {
        float v = s + b2[0];
        g_imp[r] = 1.0f / (1.0f + expf(-v));
    }
}

// ---------------- per-batch min/max normalization + floor --------------------
__global__ void k_norm_imp() {
    int b = blockIdx.x;
    int tid = threadIdx.x;        // 512
    int warp = tid >> 5, lane = tid & 31;
    __shared__ float smn[16], smx[16];
    __shared__ float bmn, bmx;
    float v = g_imp[b * SEQ + tid];
    float mn = v, mx = v;
    #pragma unroll
    for (int o = 16; o; o >>= 1) {
        mn = fminf(mn, __shfl_down_sync(0xffffffffu, mn, o));
        mx = fmaxf(mx, __shfl_down_sync(0xffffffffu, mx, o));
    }
    if (lane == 0) { smn[warp] = mn; smx[warp] = mx; }
    __syncthreads();
    if (warp == 0) {
        float a = (lane < 16) ? smn[lane] : 3.402823466e+38f;
        float c = (lane < 16) ? smx[lane] : NEG_INF;
        #pragma unroll
        for (int o = 8; o; o >>= 1) {
            a = fminf(a, __shfl_down_sync(0xffffffffu, a, o));
            c = fmaxf(c, __shfl_down_sync(0xffffffffu, c, o));
        }
        if (lane == 0) { bmn = a; bmx = c; }
    }
    __syncthreads();
    float mn0 = bmn, mx0 = bmx;
    float nv = (mx0 > mn0) ? (v - mn0) / (mx0 - mn0) : v;
    g_w[b * SEQ + tid] = fmaxf(nv, 0.1f);
}

// ---------------- token L2-normalize -----------------------------------------
__global__ void k_xnorm(const float* __restrict__ x) {
    int tk = blockIdx.x;
    const float4* xr = (const float4*)(x + (size_t)tk * DIM);
    float4* o = (float4*)(g_xn + (size_t)tk * DIM);
    int tid = threadIdx.x;        // 256
    int warp = tid >> 5, lane = tid & 31;
    float ss = 0.0f;
    #pragma unroll
    for (int c = tid; c < DIM / 4; c += 256) {
        float4 v = xr[c];
        ss += v.x * v.x + v.y * v.y + v.z * v.z + v.w * v.w;
    }
    __shared__ float sp[8];
    __shared__ float sden;
    #pragma unroll
    for (int off = 16; off; off >>= 1) ss += __shfl_down_sync(0xffffffffu, ss, off);
    if (lane == 0) sp[warp] = ss;
    __syncthreads();
    if (tid == 0) {
        float t = 0.0f;
        #pragma unroll
        for (int i = 0; i < 8; i++) t += sp[i];
        sden = fmaxf(sqrtf(t), 1e-12f);
    }
    __syncthreads();
    float d = sden;
    #pragma unroll
    for (int c = tid; c < DIM / 4; c += 256) {
        float4 v = xr[c];
        v.x /= d; v.y /= d; v.z /= d; v.w /= d;
        o[c] = v;
    }
}

// ------- similarity GEMM (xn @ xn^T), double-buffered, + score epilogue ------
// A and B tiles use identical load/compute code with commuted operands, so
// score[i][j] and score[j][i] are bitwise equal (selection tie-break relies on it).
__global__ void k_sim() {
    int b = blockIdx.z;
    const float* Xb = g_xn + (size_t)b * SEQ * DIM;
    float* Sc = g_score + (size_t)b * SEQ * SEQ;
    const float* Wb = g_w + b * SEQ;

    __shared__ float As[2][8][128];
    __shared__ float Bs[2][8][128];
    int tid = threadIdx.x;
    int bx = blockIdx.x, by = blockIdx.y;
    const float* Ab = Xb + (size_t)(by * 128) * DIM;
    const float* Bb = Xb + (size_t)(bx * 128) * DIM;
    int aRow = tid >> 1, aCol = (tid & 1) * 4;
    int ty = tid >> 4, tx = tid & 15;
    float acc[8][8];
    #pragma unroll
    for (int m = 0; m < 8; m++)
        #pragma unroll
        for (int n = 0; n < 8; n++) acc[m][n] = 0.0f;

    {
        float4 a4 = *(const float4*)(Ab + (size_t)aRow * DIM + aCol);
        As[0][aCol + 0][aRow] = a4.x;
        As[0][aCol + 1][aRow] = a4.y;
        As[0][aCol + 2][aRow] = a4.z;
        As[0][aCol + 3][aRow] = a4.w;
        float4 b4 = *(const float4*)(Bb + (size_t)aRow * DIM + aCol);
        Bs[0][aCol + 0][aRow] = b4.x;
        Bs[0][aCol + 1][aRow] = b4.y;
        Bs[0][aCol + 2][aRow] = b4.z;
        Bs[0][aCol + 3][aRow] = b4.w;
    }
    __syncthreads();

    const int nk = DIM >> 3;
    for (int t = 0; t < nk; t++) {
        int cur = t & 1;
        float4 a4n, b4n;
        if (t + 1 < nk) {
            int k0 = (t + 1) << 3;
            a4n = *(const float4*)(Ab + (size_t)aRow * DIM + k0 + aCol);
            b4n = *(const float4*)(Bb + (size_t)aRow * DIM + k0 + aCol);
        }
        #pragma unroll
        for (int kk = 0; kk < 8; kk++) {
            float af[8], bf[8];
            *(float4*)(af)     = *(const float4*)&As[cur][kk][ty * 8];
            *(float4*)(af + 4) = *(const float4*)&As[cur][kk][ty * 8 + 4];
            *(float4*)(bf)     = *(const float4*)&Bs[cur][kk][tx * 8];
            *(float4*)(bf + 4) = *(const float4*)&Bs[cur][kk][tx * 8 + 4];
            #pragma unroll
            for (int m = 0; m < 8; m++)
                #pragma unroll
                for (int n = 0; n < 8; n++)
                    acc[m][n] = fmaf(af[m], bf[n], acc[m][n]);
        }
        if (t + 1 < nk) {
            int nxt = cur ^ 1;
            As[nxt][aCol + 0][aRow] = a4n.x;
            As[nxt][aCol + 1][aRow] = a4n.y;
            As[nxt][aCol + 2][aRow] = a4n.z;
            As[nxt][aCol + 3][aRow] = a4n.w;
            Bs[nxt][aCol + 0][aRow] = b4n.x;
            Bs[nxt][aCol + 1][aRow] = b4n.y;
            Bs[nxt][aCol + 2][aRow] = b4n.z;
            Bs[nxt][aCol + 3][aRow] = b4n.w;
        }
        __syncthreads();
    }

    #pragma unroll
    for (int m = 0; m < 8; m++) {
        int i = by * 128 + ty * 8 + m;
        float wi = Wb[i];
        #pragma unroll
        for (int n4 = 0; n4 < 8; n4 += 4) {
            int j = bx * 128 + tx * 8 + n4;
            float4 v;
            v.x = (i == j + 0) ? -1.0f : acc[m][n4 + 0] / (wi * Wb[j + 0]);
            v.y = (i == j + 1) ? -1.0f : acc[m][n4 + 1] / (wi * Wb[j + 1]);
            v.z = (i == j + 2) ? -1.0f : acc[m][n4 + 2] / (wi * Wb[j + 2]);
            v.w = (i == j + 3) ? -1.0f : acc[m][n4 + 3] / (wi * Wb[j + 3]);
            *(float4*)(Sc + (size_t)i * SEQ + j) = v;
        }
    }
}

// ---------------- greedy pair selection (one CTA per batch) ------------------
// Maintains per-row (max, argmax) over available columns; recomputes only rows
// whose argmax was invalidated. Tie-break: value, then smallest flat index
// (smallest col within a row, smallest row globally) == jnp.argmax semantics.
__global__ void __launch_bounds__(512) k_greedy() {
    int b = blockIdx.x;
    const float* Sm = g_score + (size_t)b * SEQ * SEQ;
    __shared__ float rmax[SEQ];
    __shared__ int   rarg[SEQ];
    __shared__ int   avail[SEQ];
    __shared__ float pv[16];
    __shared__ int   pidx[16];
    __shared__ int   list[SEQ];
    __shared__ int   listn;
    __shared__ int   s_i, s_j;
    int tid = threadIdx.x, warp = tid >> 5, lane = tid & 31;
    avail[tid] = 1;
    __syncthreads();

    // init row maxima: one warp per row, strided
    for (int r = warp; r < SEQ; r += 16) {
        float best = NEG_INF; int bj = 0;
        for (int c = lane; c < SEQ; c += 32) {
            float v = Sm[r * SEQ + c];
            if (v > best) { best = v; bj = c; }
        }
        #pragma unroll
        for (int o = 16; o; o >>= 1) {
            float ov = __shfl_down_sync(0xffffffffu, best, o);
            int   oj = __shfl_down_sync(0xffffffffu, bj, o);
            if (ov > best || (ov == best && oj < bj)) { best = ov; bj = oj; }
        }
        if (lane == 0) { rmax[r] = best; rarg[r] = bj; }
    }
    __syncthreads();

    for (int t = 0; t < NPAIR; t++) {
        float v = avail[tid] ? rmax[tid] : NEG_INF;
        int ridx = tid;
        #pragma unroll
        for (int o = 16; o; o >>= 1) {
            float ov = __shfl_down_sync(0xffffffffu, v, o);
            int   oi = __shfl_down_sync(0xffffffffu, ridx, o);
            if (ov > v || (ov == v && oi < ridx)) { v = ov; ridx = oi; }
        }
        if (lane == 0) { pv[warp] = v; pidx[warp] = ridx; }
        __syncthreads();
        if (warp == 0) {
            float v2 = (lane < 16) ? pv[lane] : NEG_INF;
            int   i2 = (lane < 16) ? pidx[lane] : 0x7fffffff;
            #pragma unroll
            for (int o = 8; o; o >>= 1) {
                float ov = __shfl_down_sync(0xffffffffu, v2, o);
                int   oi = __shfl_down_sync(0xffffffffu, i2, o);
                if (ov > v2 || (ov == v2 && oi < i2)) { v2 = ov; i2 = oi; }
            }
            if (lane == 0) {
                int i = i2, j = rarg[i2];
                s_i = i; s_j = j;
                g_pi[b * NPAIR + t] = i;
                g_pj[b * NPAIR + t] = j;
                avail[i] = 0; avail[j] = 0;
                listn = 0;
            }
        }
        __syncthreads();
        int i = s_i, j = s_j;
        if (avail[tid] && (rarg[tid] == i || rarg[tid] == j)) {
            int p = atomicAdd(&listn, 1);
            list[p] = tid;
        }
        __syncthreads();
        int n = listn;
        for (int li = warp; li < n; li += 16) {
            int r = list[li];
            float best = NEG_INF; int bj = 0;
            for (int c = lane; c < SEQ; c += 32) {
                if (avail[c]) {
                    float vv = Sm[r * SEQ + c];
                    if (vv > best) { best = vv; bj = c; }
                }
            }
            #pragma unroll
            for (int o = 16; o; o >>= 1) {
                float ov = __shfl_down_sync(0xffffffffu, best, o);
                int   oj = __shfl_down_sync(0xffffffffu, bj, o);
                if (ov > best || (ov == best && oj < bj)) { best = ov; bj = oj; }
            }
            if (lane == 0) { rmax[r] = best; rarg[r] = bj; }
        }
        __syncthreads();
    }

    if (tid == 0) {
        int c = 0;
        for (int s2 = 0; s2 < SEQ; s2++)
            if (avail[s2]) g_un[b * NUN + c++] = s2;
    }
}

// ---------------- gathers ----------------------------------------------------
__global__ void k_gather_pair(const float* __restrict__ x) {
    int p = blockIdx.x, b = blockIdx.y;
    int i = g_pi[b * NPAIR + p];
    int j = g_pj[b * NPAIR + p];
    const float4* xi = (const float4*)(x + ((size_t)b * SEQ + i) * DIM);
    const float4* xj = (const float4*)(x + ((size_t)b * SEQ + j) * DIM);
    float4* dst = (float4*)(g_pair + (size_t)(b * NPAIR + p) * 2 * DIM);
    int tid = threadIdx.x;  // 256
    #pragma unroll
    for (int c = tid; c < DIM / 4; c += 256) {
        dst[c] = xi[c];
        dst[DIM / 4 + c] = xj[c];
    }
}

__global__ void k_gather_un(const float* __restrict__ x, float* __restrict__ out) {
    int u = blockIdx.x, b = blockIdx.y;
    int idx = g_un[b * NUN + u];
    const float4* src = (const float4*)(x + ((size_t)b * SEQ + idx) * DIM);
    float4* dst = (float4*)(out + ((size_t)(b * 384 + NPAIR + u)) * DIM);
    int tid = threadIdx.x;
    #pragma unroll
    for (int c = tid; c < DIM / 4; c += 256) dst[c] = src[c];
}

// ---------------- launch -----------------------------------------------------
extern "C" void kernel_launch(void* const* d_in, const int* in_sizes, int n_in,
                              void* d_out, int out_size) {
    const float* x      = (const float*)d_in[0];
    const float* imp_w1 = (const float*)d_in[1];
    const float* imp_b1 = (const float*)d_in[2];
    const float* imp_w2 = (const float*)d_in[3];
    const float* imp_b2 = (const float*)d_in[4];
    const float* mrg_w1 = (const float*)d_in[5];
    const float* mrg_b1 = (const float*)d_in[6];
    const float* mrg_w2 = (const float*)d_in[7];
    const float* mrg_b2 = (const float*)d_in[8];
    float* out = (float*)d_out;

    // 1) importance MLP hidden: g_h = gelu(x @ imp_w1 + b1)
    k_imp_gemm<<<dim3(HID / 128, ROWS / 128), 256>>>(x, imp_w1, imp_b1);
    // 2) imp = sigmoid(g_h . w2 + b2)
    k_imp<<<ROWS / 8, 256>>>(imp_w2, imp_b2);
    // 3) per-batch min-max norm + floor -> g_w
    k_norm_imp<<<BATCH, SEQ>>>();
    // 4) xn = x / max(||x||, 1e-12)
    k_xnorm<<<ROWS, 256>>>(x);
    // 5) score = (xn @ xn^T)/(wi*wj), diag=-1
    k_sim<<<dim3(SEQ / 128, SEQ / 128, BATCH), 256>>>();
    // 6) greedy pair selection
    k_greedy<<<BATCH, SEQ>>>();
    // 7) gathers
    k_gather_pair<<<dim3(NPAIR, BATCH), 256>>>(x);
    k_gather_un<<<dim3(NUN, BATCH), 256>>>(x, out);
    // 8) merger MLP
    k_mrg_gemm1<<<dim3(DIM / 128, MROWS / 128), 256>>>(mrg_w1, mrg_b1);
    k_mrg_gemm2<<<dim3(DIM / 128, MROWS / 128), 256>>>(mrg_w2, mrg_b2, out);

    (void)in_sizes; (void)n_in; (void)out_size;
}

// round 8
// speedup vs baseline: 1.1347x; 1.1347x over previous
#include <cuda_runtime.h>
#include <cuda_bf16.h>
#include <math.h>
#include <stdint.h>

#define BATCH 16
#define SEQ   512
#define DIM   2048
#define HID   1024
#define NPAIR 128
#define NUN   256
#define ROWS  (BATCH*SEQ)    /* 8192 */
#define MROWS (BATCH*NPAIR)  /* 2048 */

#define NEG_INF (-3.402823466e+38f)

// ---------------- scratch (static device globals; no allocs allowed) ----------
__device__ float g_h[(size_t)ROWS * HID];            // 32 MB  GELU hidden
__device__ float g_imp[ROWS];                        // sigmoid scores
__device__ float g_w[ROWS];                          // clamped normalized importance
__device__ float g_xn[(size_t)ROWS * DIM];           // 64 MB  normalized x
__device__ float g_score[(size_t)BATCH * SEQ * SEQ]; // 16 MB  combined scores
__device__ int   g_pi[BATCH * NPAIR];
__device__ int   g_pj[BATCH * NPAIR];
__device__ int   g_un[BATCH * NUN];

// bf16-split merger MLP buffers
__device__ __nv_bfloat16 g_pair_h[(size_t)MROWS * 2 * DIM];  // [2048][4096]
__device__ __nv_bfloat16 g_pair_l[(size_t)MROWS * 2 * DIM];
__device__ __nv_bfloat16 g_w1t_h[(size_t)DIM * 2 * DIM];     // transposed [2048][4096]
__device__ __nv_bfloat16 g_w1t_l[(size_t)DIM * 2 * DIM];
__device__ __nv_bfloat16 g_hid_h[(size_t)MROWS * DIM];       // [2048][2048]
__device__ __nv_bfloat16 g_hid_l[(size_t)MROWS * DIM];
__device__ __nv_bfloat16 g_w2t_h[(size_t)DIM * DIM];         // transposed [2048][2048]
__device__ __nv_bfloat16 g_w2t_l[(size_t)DIM * DIM];

// ---------------- helpers ----------------------------------------------------
__device__ __forceinline__ float gelu_erf(float v) {
    return 0.5f * v * (1.0f + erff(v * 0.70710678118654752440f));
}

// ------- generic 128x128x8 SGEMM body, double-buffered smem pipeline ---------
// (fp32 exact path — importance GEMM only; numerics must stay fp32)
__device__ __forceinline__ void sgemm_body(
    const float* __restrict__ A, const float* __restrict__ B,
    const float* __restrict__ bias, float* __restrict__ C,
    int M, int N, int K)
{
    __shared__ float As[2][8][128];
    __shared__ float Bs[2][8][128];
    int tid = threadIdx.x;                // 256 threads
    int bx = blockIdx.x, by = blockIdx.y;
    const float* Ab = A + (size_t)(by * 128) * K;
    const float* Bb = B + bx * 128;
    int aRow = tid >> 1, aCol = (tid & 1) * 4;
    int bRow = tid >> 5, bCol = (tid & 31) * 4;
    int ty = tid >> 4,  tx = tid & 15;
    float acc[8][8];
    #pragma unroll
    for (int m = 0; m < 8; m++)
        #pragma unroll
        for (int n = 0; n < 8; n++) acc[m][n] = 0.0f;

    {
        float4 a4 = *(const float4*)(Ab + (size_t)aRow * K + aCol);
        As[0][aCol + 0][aRow] = a4.x;
        As[0][aCol + 1][aRow] = a4.y;
        As[0][aCol + 2][aRow] = a4.z;
        As[0][aCol + 3][aRow] = a4.w;
        float4 b4 = *(const float4*)(Bb + (size_t)bRow * N + bCol);
        *(float4*)&Bs[0][bRow][bCol] = b4;
    }
    __syncthreads();

    int nk = K >> 3;
    for (int t = 0; t < nk; t++) {
        int cur = t & 1;
        float4 a4n, b4n;
        if (t + 1 < nk) {
            int k0 = (t + 1) << 3;
            a4n = *(const float4*)(Ab + (size_t)aRow * K + k0 + aCol);
            b4n = *(const float4*)(Bb + (size_t)(k0 + bRow) * N + bCol);
        }
        #pragma unroll
        for (int kk = 0; kk < 8; kk++) {
            float af[8], bf[8];
            *(float4*)(af)     = *(const float4*)&As[cur][kk][ty * 8];
            *(float4*)(af + 4) = *(const float4*)&As[cur][kk][ty * 8 + 4];
            *(float4*)(bf)     = *(const float4*)&Bs[cur][kk][tx * 8];
            *(float4*)(bf + 4) = *(const float4*)&Bs[cur][kk][tx * 8 + 4];
            #pragma unroll
            for (int m = 0; m < 8; m++)
                #pragma unroll
                for (int n = 0; n < 8; n++)
                    acc[m][n] = fmaf(af[m], bf[n], acc[m][n]);
        }
        if (t + 1 < nk) {
            int nxt = cur ^ 1;
            As[nxt][aCol + 0][aRow] = a4n.x;
            As[nxt][aCol + 1][aRow] = a4n.y;
            As[nxt][aCol + 2][aRow] = a4n.z;
            As[nxt][aCol + 3][aRow] = a4n.w;
            *(float4*)&Bs[nxt][bRow][bCol] = b4n;
        }
        __syncthreads();
    }

    #pragma unroll
    for (int m = 0; m < 8; m++) {
        int row = by * 128 + ty * 8 + m;
        #pragma unroll
        for (int n4 = 0; n4 < 8; n4 += 4) {
            int col = bx * 128 + tx * 8 + n4;
            float4 v;
            v.x = gelu_erf(acc[m][n4 + 0] + bias[col + 0]);
            v.y = gelu_erf(acc[m][n4 + 1] + bias[col + 1]);
            v.z = gelu_erf(acc[m][n4 + 2] + bias[col + 2]);
            v.w = gelu_erf(acc[m][n4 + 3] + bias[col + 3]);
            *(float4*)(C + (size_t)row * N + col) = v;
        }
    }
}

__global__ void k_imp_gemm(const float* __restrict__ x,
                           const float* __restrict__ w1,
                           const float* __restrict__ b1) {
    sgemm_body(x, w1, b1, g_h, ROWS, HID, DIM);
}

// ================== bf16-split tensor-core GEMM (merger MLP) =================
// C = (Ah+Al) @ (Bh+Bl)^T via 3 products (drop Al*Bl), fp32 accum.
// A: [M][K] row-major hi/lo bf16. B: transposed weights [N][K] hi/lo bf16.
// mode 0: v = gelu(acc+bias) -> split-write outH/outL [row][2048]
// mode 1: v = acc+bias -> outF[((row>>7)*384 + (row&127))*2048 + col]

#define CP16(d, p) asm volatile("cp.async.ca.shared.global [%0], [%1], 16;\n" :: "r"(d), "l"(p))
#define CP_COMMIT  asm volatile("cp.async.commit_group;\n")
#define CP_WAIT1   asm volatile("cp.async.wait_group 1;\n" ::: "memory")
#define CP_WAIT0   asm volatile("cp.async.wait_group 0;\n" ::: "memory")

__device__ __forceinline__ void mma16816(float c[4], const unsigned a[4], const unsigned b[2]) {
    asm volatile(
        "mma.sync.aligned.m16n8k16.row.col.f32.bf16.bf16.f32 "
        "{%0,%1,%2,%3}, {%4,%5,%6,%7}, {%8,%9}, {%0,%1,%2,%3};\n"
        : "+f"(c[0]), "+f"(c[1]), "+f"(c[2]), "+f"(c[3])
        : "r"(a[0]), "r"(a[1]), "r"(a[2]), "r"(a[3]), "r"(b[0]), "r"(b[1]));
}

#define SMPAD 24  /* bf16 elems per row (16 data + 8 pad); 48B: 16B-aligned, conflict-free */

// A fragment m16k16 from s[m][k] (stride SMPAD)
__device__ __forceinline__ void lda16(unsigned a[4], const __nv_bfloat16* s, int m0, int lane) {
    int g = lane >> 2, tg = (lane & 3) * 2;
    const __nv_bfloat16* p = s + (m0 + g) * SMPAD + tg;
    a[0] = *(const unsigned*)(p);
    a[1] = *(const unsigned*)(p + 8 * SMPAD);
    a[2] = *(const unsigned*)(p + 8);
    a[3] = *(const unsigned*)(p + 8 * SMPAD + 8);
}
// B fragment k16n8 from s[n][k] (stride SMPAD)
__device__ __forceinline__ void ldb16(unsigned b[2], const __nv_bfloat16* s, int n0, int lane) {
    int g = lane >> 2, tg = (lane & 3) * 2;
    const __nv_bfloat16* p = s + (n0 + g) * SMPAD + tg;
    b[0] = *(const unsigned*)(p);
    b[1] = *(const unsigned*)(p + 8);
}

__device__ __forceinline__ void mma_gemm_body(
    const __nv_bfloat16* __restrict__ Ah, const __nv_bfloat16* __restrict__ Al,
    const __nv_bfloat16* __restrict__ Bh, const __nv_bfloat16* __restrict__ Bl,
    const float* __restrict__ bias, int K, int mode,
    __nv_bfloat16* __restrict__ outH, __nv_bfloat16* __restrict__ outL,
    float* __restrict__ outF)
{
    // smem: [stage][mat: Ah,Al,Bh,Bl][128 rows * SMPAD] = 2*4*128*24*2B = 48KB
    __shared__ __align__(16) __nv_bfloat16 sm[2][4][128 * SMPAD];
    int tid = threadIdx.x, lane = tid & 31, wid = tid >> 5;
    int wm = wid & 1, wn = wid >> 1;              // warp tile 64x32 in 2x4 grid
    int bm = blockIdx.y, bn = blockIdx.x;

    float acc[4][4][4];
    #pragma unroll
    for (int m = 0; m < 4; m++)
        #pragma unroll
        for (int n = 0; n < 4; n++)
            #pragma unroll
            for (int r = 0; r < 4; r++) acc[m][n][r] = 0.0f;

    // cp.async mapping: 256 threads; r=tid&127 row, half: 0->A mats, 1->B mats
    int r = tid & 127, half = tid >> 7;
    const __nv_bfloat16* gh;
    const __nv_bfloat16* gl;
    if (half == 0) { gh = Ah + (size_t)(bm * 128 + r) * K; gl = Al + (size_t)(bm * 128 + r) * K; }
    else           { gh = Bh + (size_t)(bn * 128 + r) * K; gl = Bl + (size_t)(bn * 128 + r) * K; }
    unsigned sbH0 = (unsigned)__cvta_generic_to_shared(&sm[0][half * 2    ][r * SMPAD]);
    unsigned sbL0 = (unsigned)__cvta_generic_to_shared(&sm[0][half * 2 + 1][r * SMPAD]);
    const unsigned stageStride = 4 * 128 * SMPAD * 2;  // bytes between stages

    int nk = K >> 4;
    // prologue: stage 0
    {
        CP16(sbH0,      gh);  CP16(sbH0 + 16, gh + 8);
        CP16(sbL0,      gl);  CP16(sbL0 + 16, gl + 8);
        CP_COMMIT;
    }
    for (int t = 0; t < nk; t++) {
        if (t + 1 < nk) {
            int k0 = (t + 1) << 4;
            unsigned off = ((t + 1) & 1) ? stageStride : 0;
            CP16(sbH0 + off,      gh + k0);  CP16(sbH0 + off + 16, gh + k0 + 8);
            CP16(sbL0 + off,      gl + k0);  CP16(sbL0 + off + 16, gl + k0 + 8);
            CP_COMMIT;
            CP_WAIT1;
        } else {
            CP_WAIT0;
        }
        __syncthreads();
        int s = t & 1;
        const __nv_bfloat16* pAh = &sm[s][0][0];
        const __nv_bfloat16* pAl = &sm[s][1][0];
        const __nv_bfloat16* pBh = &sm[s][2][0];
        const __nv_bfloat16* pBl = &sm[s][3][0];

        unsigned fah[4][4], fal[4][4], fbh[4][2], fbl[4][2];
        #pragma unroll
        for (int mt = 0; mt < 4; mt++) {
            lda16(fah[mt], pAh, wm * 64 + mt * 16, lane);
            lda16(fal[mt], pAl, wm * 64 + mt * 16, lane);
        }
        #pragma unroll
        for (int nt = 0; nt < 4; nt++) {
            ldb16(fbh[nt], pBh, wn * 32 + nt * 8, lane);
            ldb16(fbl[nt], pBl, wn * 32 + nt * 8, lane);
        }
        #pragma unroll
        for (int mt = 0; mt < 4; mt++)
            #pragma unroll
            for (int nt = 0; nt < 4; nt++) {
                mma16816(acc[mt][nt], fah[mt], fbh[nt]);
                mma16816(acc[mt][nt], fah[mt], fbl[nt]);
                mma16816(acc[mt][nt], fal[mt], fbh[nt]);
            }
        __syncthreads();
    }

    // epilogue: c0:(g, 2tg) c1:(g, 2tg+1) c2:(g+8, 2tg) c3:(g+8, 2tg+1)
    int g = lane >> 2, tg = (lane & 3) * 2;
    #pragma unroll
    for (int mt = 0; mt < 4; mt++) {
        #pragma unroll
        for (int nt = 0; nt < 4; nt++) {
            int col = bn * 128 + wn * 32 + nt * 8 + tg;
            float bx0 = bias[col], bx1 = bias[col + 1];
            #pragma unroll
            for (int h = 0; h < 2; h++) {
                int row = bm * 128 + wm * 64 + mt * 16 + g + 8 * h;
                float v0 = acc[mt][nt][2 * h]     + bx0;
                float v1 = acc[mt][nt][2 * h + 1] + bx1;
                if (mode == 0) {
                    v0 = gelu_erf(v0); v1 = gelu_erf(v1);
                    __nv_bfloat16 h0 = __float2bfloat16(v0);
                    __nv_bfloat16 h1 = __float2bfloat16(v1);
                    size_t o = (size_t)row * DIM + col;
                    outH[o]     = h0; outL[o]     = __float2bfloat16(v0 - __bfloat162float(h0));
                    outH[o + 1] = h1; outL[o + 1] = __float2bfloat16(v1 - __bfloat162float(h1));
                } else {
                    int orow = (row >> 7) * 384 + (row & 127);
                    size_t o = (size_t)orow * DIM + col;
                    outF[o] = v0; outF[o + 1] = v1;
                }
            }
        }
    }
}

__global__ void __launch_bounds__(256) k_mma_mrg1(const float* __restrict__ b1) {
    mma_gemm_body(g_pair_h, g_pair_l, g_w1t_h, g_w1t_l, b1, 2 * DIM, 0,
                  g_hid_h, g_hid_l, (float*)0);
}
__global__ void __launch_bounds__(256) k_mma_mrg2(const float* __restrict__ b2,
                                                  float* __restrict__ out) {
    mma_gemm_body(g_hid_h, g_hid_l, g_w2t_h, g_w2t_l, b2, DIM, 1,
                  (__nv_bfloat16*)0, (__nv_bfloat16*)0, out);
}

// -------- weight transpose + bf16 hi/lo split:  W[K][N] -> T[N][K] -----------
__device__ __forceinline__ void cvt_wT_body(const float* __restrict__ W,
                                            __nv_bfloat16* __restrict__ Th,
                                            __nv_bfloat16* __restrict__ Tl,
                                            int K, int N) {
    __shared__ float tile[32][33];
    int k0 = blockIdx.y * 32, n0 = blockIdx.x * 32;
    int tx = threadIdx.x, ty = threadIdx.y;   // 32 x 8
    #pragma unroll
    for (int i = ty; i < 32; i += 8)
        tile[i][tx] = W[(size_t)(k0 + i) * N + n0 + tx];
    __syncthreads();
    #pragma unroll
    for (int i = ty; i < 32; i += 8) {
        float v = tile[tx][i];   // = W[k0+tx][n0+i]
        __nv_bfloat16 h = __float2bfloat16(v);
        size_t o = (size_t)(n0 + i) * K + k0 + tx;
        Th[o] = h;
        Tl[o] = __float2bfloat16(v - __bfloat162float(h));
    }
}
__global__ void k_cvt_w1t(const float* __restrict__ w1) { cvt_wT_body(w1, g_w1t_h, g_w1t_l, 2 * DIM, DIM); }
__global__ void k_cvt_w2t(const float* __restrict__ w2) { cvt_wT_body(w2, g_w2t_h, g_w2t_l, DIM, DIM); }

// -------- pair gather + bf16 hi/lo split -------------------------------------
__global__ void k_cvt_pair(const float* __restrict__ x) {
    int p = blockIdx.x, b = blockIdx.y;
    int i = g_pi[b * NPAIR + p];
    int j = g_pj[b * NPAIR + p];
    const float* xi = x + ((size_t)b * SEQ + i) * DIM;
    const float* xj = x + ((size_t)b * SEQ + j) * DIM;
    size_t ro = (size_t)(b * NPAIR + p) * 2 * DIM;
    for (int c = threadIdx.x; c < DIM; c += 256) {
        float v = xi[c];
        __nv_bfloat16 h = __float2bfloat16(v);
        g_pair_h[ro + c] = h;
        g_pair_l[ro + c] = __float2bfloat16(v - __bfloat162float(h));
        float w = xj[c];
        __nv_bfloat16 h2 = __float2bfloat16(w);
        g_pair_h[ro + DIM + c] = h2;
        g_pair_l[ro + DIM + c] = __float2bfloat16(w - __bfloat162float(h2));
    }
}

// ---------------- importance GEMV + sigmoid (one warp per row) ---------------
__global__ void k_imp(const float* __restrict__ w2, const float* __restrict__ b2) {
    int r = blockIdx.x * 8 + (threadIdx.x >> 5);
    int lane = threadIdx.x & 31;
    const float* hr = g_h + (size_t)r * HID;
    float s = 0.0f;
    for (int c = lane; c < HID; c += 32) s = fmaf(hr[c], w2[c], s);
    #pragma unroll
    for (int o = 16; o; o >>= 1) s += __shfl_down_sync(0xffffffffu, s, o);
    if (lane == 0) {
        float v = s + b2[0];
        g_imp[r] = 1.0f / (1.0f + expf(-v));
    }
}

// ---------------- per-batch min/max normalization + floor --------------------
__global__ void k_norm_imp() {
    int b = blockIdx.x;
    int tid = threadIdx.x;        // 512
    int warp = tid >> 5, lane = tid & 31;
    __shared__ float smn[16], smx[16];
    __shared__ float bmn, bmx;
    float v = g_imp[b * SEQ + tid];
    float mn = v, mx = v;
    #pragma unroll
    for (int o = 16; o; o >>= 1) {
        mn = fminf(mn, __shfl_down_sync(0xffffffffu, mn, o));
        mx = fmaxf(mx, __shfl_down_sync(0xffffffffu, mx, o));
    }
    if (lane == 0) { smn[warp] = mn; smx[warp] = mx; }
    __syncthreads();
    if (warp == 0) {
        float a = (lane < 16) ? smn[lane] : 3.402823466e+38f;
        float c = (lane < 16) ? smx[lane] : NEG_INF;
        #pragma unroll
        for (int o = 8; o; o >>= 1) {
            a = fminf(a, __shfl_down_sync(0xffffffffu, a, o));
            c = fmaxf(c, __shfl_down_sync(0xffffffffu, c, o));
        }
        if (lane == 0) { bmn = a; bmx = c; }
    }
    __syncthreads();
    float mn0 = bmn, mx0 = bmx;
    float nv = (mx0 > mn0) ? (v - mn0) / (mx0 - mn0) : v;
    g_w[b * SEQ + tid] = fmaxf(nv, 0.1f);
}

// ---------------- token L2-normalize -----------------------------------------
__global__ void k_xnorm(const float* __restrict__ x) {
    int tk = blockIdx.x;
    const float4* xr = (const float4*)(x + (size_t)tk * DIM);
    float4* o = (float4*)(g_xn + (size_t)tk * DIM);
    int tid = threadIdx.x;        // 256
    int warp = tid >> 5, lane = tid & 31;
    float ss = 0.0f;
    #pragma unroll
    for (int c = tid; c < DIM / 4; c += 256) {
        float4 v = xr[c];
        ss += v.x * v.x + v.y * v.y + v.z * v.z + v.w * v.w;
    }
    __shared__ float sp[8];
    __shared__ float sden;
    #pragma unroll
    for (int off = 16; off; off >>= 1) ss += __shfl_down_sync(0xffffffffu, ss, off);
    if (lane == 0) sp[warp] = ss;
    __syncthreads();
    if (tid == 0) {
        float t = 0.0f;
        #pragma unroll
        for (int i = 0; i < 8; i++) t += sp[i];
        sden = fmaxf(sqrtf(t), 1e-12f);
    }
    __syncthreads();
    float d = sden;
    #pragma unroll
    for (int c = tid; c < DIM / 4; c += 256) {
        float4 v = xr[c];
        v.x /= d; v.y /= d; v.z /= d; v.w /= d;
        o[c] = v;
    }
}

// ------- similarity GEMM (xn @ xn^T), double-buffered, + score epilogue ------
// A and B tiles use identical load/compute code with commuted operands, so
// score[i][j] and score[j][i] are bitwise equal (selection tie-break relies on it).
__global__ void k_sim() {
    int b = blockIdx.z;
    const float* Xb = g_xn + (size_t)b * SEQ * DIM;
    float* Sc = g_score + (size_t)b * SEQ * SEQ;
    const float* Wb = g_w + b * SEQ;

    __shared__ float As[2][8][128];
    __shared__ float Bs[2][8][128];
    int tid = threadIdx.x;
    int bx = blockIdx.x, by = blockIdx.y;
    const float* Ab = Xb + (size_t)(by * 128) * DIM;
    const float* Bb = Xb + (size_t)(bx * 128) * DIM;
    int aRow = tid >> 1, aCol = (tid & 1) * 4;
    int ty = tid >> 4, tx = tid & 15;
    float acc[8][8];
    #pragma unroll
    for (int m = 0; m < 8; m++)
        #pragma unroll
        for (int n = 0; n < 8; n++) acc[m][n] = 0.0f;

    {
        float4 a4 = *(const float4*)(Ab + (size_t)aRow * DIM + aCol);
        As[0][aCol + 0][aRow] = a4.x;
        As[0][aCol + 1][aRow] = a4.y;
        As[0][aCol + 2][aRow] = a4.z;
        As[0][aCol + 3][aRow] = a4.w;
        float4 b4 = *(const float4*)(Bb + (size_t)aRow * DIM + aCol);
        Bs[0][aCol + 0][aRow] = b4.x;
        Bs[0][aCol + 1][aRow] = b4.y;
        Bs[0][aCol + 2][aRow] = b4.z;
        Bs[0][aCol + 3][aRow] = b4.w;
    }
    __syncthreads();

    const int nk = DIM >> 3;
    for (int t = 0; t < nk; t++) {
        int cur = t & 1;
        float4 a4n, b4n;
        if (t + 1 < nk) {
            int k0 = (t + 1) << 3;
            a4n = *(const float4*)(Ab + (size_t)aRow * DIM + k0 + aCol);
            b4n = *(const float4*)(Bb + (size_t)aRow * DIM + k0 + aCol);
        }
        #pragma unroll
        for (int kk = 0; kk < 8; kk++) {
            float af[8], bf[8];
            *(float4*)(af)     = *(const float4*)&As[cur][kk][ty * 8];
            *(float4*)(af + 4) = *(const float4*)&As[cur][kk][ty * 8 + 4];
            *(float4*)(bf)     = *(const float4*)&Bs[cur][kk][tx * 8];
            *(float4*)(bf + 4) = *(const float4*)&Bs[cur][kk][tx * 8 + 4];
            #pragma unroll
            for (int m = 0; m < 8; m++)
                #pragma unroll
                for (int n = 0; n < 8; n++)
                    acc[m][n] = fmaf(af[m], bf[n], acc[m][n]);
        }
        if (t + 1 < nk) {
            int nxt = cur ^ 1;
            As[nxt][aCol + 0][aRow] = a4n.x;
            As[nxt][aCol + 1][aRow] = a4n.y;
            As[nxt][aCol + 2][aRow] = a4n.z;
            As[nxt][aCol + 3][aRow] = a4n.w;
            Bs[nxt][aCol + 0][aRow] = b4n.x;
            Bs[nxt][aCol + 1][aRow] = b4n.y;
            Bs[nxt][aCol + 2][aRow] = b4n.z;
            Bs[nxt][aCol + 3][aRow] = b4n.w;
        }
        __syncthreads();
    }

    #pragma unroll
    for (int m = 0; m < 8; m++) {
        int i = by * 128 + ty * 8 + m;
        float wi = Wb[i];
        #pragma unroll
        for (int n4 = 0; n4 < 8; n4 += 4) {
            int j = bx * 128 + tx * 8 + n4;
            float4 v;
            v.x = (i == j + 0) ? -1.0f : acc[m][n4 + 0] / (wi * Wb[j + 0]);
            v.y = (i == j + 1) ? -1.0f : acc[m][n4 + 1] / (wi * Wb[j + 1]);
            v.z = (i == j + 2) ? -1.0f : acc[m][n4 + 2] / (wi * Wb[j + 2]);
            v.w = (i == j + 3) ? -1.0f : acc[m][n4 + 3] / (wi * Wb[j + 3]);
            *(float4*)(Sc + (size_t)i * SEQ + j) = v;
        }
    }
}

// ---------------- greedy pair selection (one CTA per batch) ------------------
__global__ void __launch_bounds__(512) k_greedy() {
    int b = blockIdx.x;
    const float* Sm = g_score + (size_t)b * SEQ * SEQ;
    __shared__ float rmax[SEQ];
    __shared__ int   rarg[SEQ];
    __shared__ int   avail[SEQ];
    __shared__ float pv[16];
    __shared__ int   pidx[16];
    __shared__ int   list[SEQ];
    __shared__ int   listn;
    __shared__ int   s_i, s_j;
    int tid = threadIdx.x, warp = tid >> 5, lane = tid & 31;
    avail[tid] = 1;
    __syncthreads();

    for (int r = warp; r < SEQ; r += 16) {
        float best = NEG_INF; int bj = 0;
        for (int c = lane; c < SEQ; c += 32) {
            float v = Sm[r * SEQ + c];
            if (v > best) { best = v; bj = c; }
        }
        #pragma unroll
        for (int o = 16; o; o >>= 1) {
            float ov = __shfl_down_sync(0xffffffffu, best, o);
            int   oj = __shfl_down_sync(0xffffffffu, bj, o);
            if (ov > best || (ov == best && oj < bj)) { best = ov; bj = oj; }
        }
        if (lane == 0) { rmax[r] = best; rarg[r] = bj; }
    }
    __syncthreads();

    for (int t = 0; t < NPAIR; t++) {
        float v = avail[tid] ? rmax[tid] : NEG_INF;
        int ridx = tid;
        #pragma unroll
        for (int o = 16; o; o >>= 1) {
            float ov = __shfl_down_sync(0xffffffffu, v, o);
            int   oi = __shfl_down_sync(0xffffffffu, ridx, o);
            if (ov > v || (ov == v && oi < ridx)) { v = ov; ridx = oi; }
        }
        if (lane == 0) { pv[warp] = v; pidx[warp] = ridx; }
        __syncthreads();
        if (warp == 0) {
            float v2 = (lane < 16) ? pv[lane] : NEG_INF;
            int   i2 = (lane < 16) ? pidx[lane] : 0x7fffffff;
            #pragma unroll
            for (int o = 8; o; o >>= 1) {
                float ov = __shfl_down_sync(0xffffffffu, v2, o);
                int   oi = __shfl_down_sync(0xffffffffu, i2, o);
                if (ov > v2 || (ov == v2 && oi < i2)) { v2 = ov; i2 = oi; }
            }
            if (lane == 0) {
                int i = i2, j = rarg[i2];
                s_i = i; s_j = j;
                g_pi[b * NPAIR + t] = i;
                g_pj[b * NPAIR + t] = j;
                avail[i] = 0; avail[j] = 0;
                listn = 0;
            }
        }
        __syncthreads();
        int i = s_i, j = s_j;
        if (avail[tid] && (rarg[tid] == i || rarg[tid] == j)) {
            int p = atomicAdd(&listn, 1);
            list[p] = tid;
        }
        __syncthreads();
        int n = listn;
        for (int li = warp; li < n; li += 16) {
            int r = list[li];
            float best = NEG_INF; int bj = 0;
            for (int c = lane; c < SEQ; c += 32) {
                if (avail[c]) {
                    float vv = Sm[r * SEQ + c];
                    if (vv > best) { best = vv; bj = c; }
                }
            }
            #pragma unroll
            for (int o = 16; o; o >>= 1) {
                float ov = __shfl_down_sync(0xffffffffu, best, o);
                int   oj = __shfl_down_sync(0xffffffffu, bj, o);
                if (ov > best || (ov == best && oj < bj)) { best = ov; bj = oj; }
            }
            if (lane == 0) { rmax[r] = best; rarg[r] = bj; }
        }
        __syncthreads();
    }

    if (tid == 0) {
        int c = 0;
        for (int s2 = 0; s2 < SEQ; s2++)
            if (avail[s2]) g_un[b * NUN + c++] = s2;
    }
}

// ---------------- unmerged gather --------------------------------------------
__global__ void k_gather_un(const float* __restrict__ x, float* __restrict__ out) {
    int u = blockIdx.x, b = blockIdx.y;
    int idx = g_un[b * NUN + u];
    const float4* src = (const float4*)(x + ((size_t)b * SEQ + idx) * DIM);
    float4* dst = (float4*)(out + ((size_t)(b * 384 + NPAIR + u)) * DIM);
    int tid = threadIdx.x;
    #pragma unroll
    for (int c = tid; c < DIM / 4; c += 256) dst[c] = src[c];
}

// ---------------- launch -----------------------------------------------------
extern "C" void kernel_launch(void* const* d_in, const int* in_sizes, int n_in,
                              void* d_out, int out_size) {
    const float* x      = (const float*)d_in[0];
    const float* imp_w1 = (const float*)d_in[1];
    const float* imp_b1 = (const float*)d_in[2];
    const float* imp_w2 = (const float*)d_in[3];
    const float* imp_b2 = (const float*)d_in[4];
    const float* mrg_w1 = (const float*)d_in[5];
    const float* mrg_b1 = (const float*)d_in[6];
    const float* mrg_w2 = (const float*)d_in[7];
    const float* mrg_b2 = (const float*)d_in[8];
    float* out = (float*)d_out;

    // weight transpose+split (independent of data path)
    k_cvt_w1t<<<dim3(DIM / 32, 2 * DIM / 32), dim3(32, 8)>>>(mrg_w1);
    k_cvt_w2t<<<dim3(DIM / 32, DIM / 32), dim3(32, 8)>>>(mrg_w2);

    // importance MLP (fp32 exact — feeds selection)
    k_imp_gemm<<<dim3(HID / 128, ROWS / 128), 256>>>(x, imp_w1, imp_b1);
    k_imp<<<ROWS / 8, 256>>>(imp_w2, imp_b2);
    k_norm_imp<<<BATCH, SEQ>>>();
    k_xnorm<<<ROWS, 256>>>(x);
    k_sim<<<dim3(SEQ / 128, SEQ / 128, BATCH), 256>>>();
    k_greedy<<<BATCH, SEQ>>>();

    // gathers
    k_cvt_pair<<<dim3(NPAIR, BATCH), 256>>>(x);
    k_gather_un<<<dim3(NUN, BATCH), 256>>>(x, out);

    // merger MLP on tensor cores (bf16-split, fp32 accum)
    k_mma_mrg1<<<dim3(DIM / 128, MROWS / 128), 256>>>(mrg_b1);
    k_mma_mrg2<<<dim3(DIM / 128, MROWS / 128), 256>>>(mrg_b2, out);

    (void)in_sizes; (void)n_in; (void)out_size;
}

// round 14
// speedup vs baseline: 1.2491x; 1.1008x over previous
#include <cuda_runtime.h>
#include <cuda_bf16.h>
#include <math.h>
#include <stdint.h>

#define BATCH 16
#define SEQ   512
#define DIM   2048
#define HID   1024
#define NPAIR 128
#define NUN   256
#define ROWS  (BATCH*SEQ)    /* 8192 */
#define MROWS (BATCH*NPAIR)  /* 2048 */

#define NEG_INF (-3.402823466e+38f)

// ---------------- scratch (static device globals; no allocs allowed) ----------
__device__ float g_h[(size_t)ROWS * HID];            // 32 MB  GELU hidden
__device__ float g_imp[ROWS];                        // sigmoid scores
__device__ float g_w[ROWS];                          // clamped normalized importance
__device__ float g_xn[(size_t)ROWS * DIM];           // 64 MB  normalized x
__device__ float g_score[(size_t)BATCH * SEQ * SEQ]; // 16 MB  combined scores
__device__ int   g_pi[BATCH * NPAIR];
__device__ int   g_pj[BATCH * NPAIR];
__device__ int   g_un[BATCH * NUN];

// bf16-split merger MLP buffers
__device__ __nv_bfloat16 g_pair_h[(size_t)MROWS * 2 * DIM];  // [2048][4096]
__device__ __nv_bfloat16 g_pair_l[(size_t)MROWS * 2 * DIM];
__device__ __nv_bfloat16 g_w1t_h[(size_t)DIM * 2 * DIM];     // transposed [2048][4096]
__device__ __nv_bfloat16 g_w1t_l[(size_t)DIM * 2 * DIM];
__device__ __nv_bfloat16 g_hid_h[(size_t)MROWS * DIM];       // [2048][2048]
__device__ __nv_bfloat16 g_hid_l[(size_t)MROWS * DIM];
__device__ __nv_bfloat16 g_w2t_h[(size_t)DIM * DIM];         // transposed [2048][2048]
__device__ __nv_bfloat16 g_w2t_l[(size_t)DIM * DIM];

// ---------------- helpers ----------------------------------------------------
__device__ __forceinline__ float gelu_erf(float v) {
    return 0.5f * v * (1.0f + erff(v * 0.70710678118654752440f));
}

// ------- generic 128x128x8 SGEMM body, double-buffered smem pipeline ---------
// (fp32 exact path — importance GEMM only; numerics must stay fp32)
__device__ __forceinline__ void sgemm_body(
    const float* __restrict__ A, const float* __restrict__ B,
    const float* __restrict__ bias, float* __restrict__ C,
    int M, int N, int K)
{
    __shared__ float As[2][8][128];
    __shared__ float Bs[2][8][128];
    int tid = threadIdx.x;                // 256 threads
    int bx = blockIdx.x, by = blockIdx.y;
    const float* Ab = A + (size_t)(by * 128) * K;
    const float* Bb = B + bx * 128;
    int aRow = tid >> 1, aCol = (tid & 1) * 4;
    int bRow = tid >> 5, bCol = (tid & 31) * 4;
    int ty = tid >> 4,  tx = tid & 15;
    float acc[8][8];
    #pragma unroll
    for (int m = 0; m < 8; m++)
        #pragma unroll
        for (int n = 0; n < 8; n++) acc[m][n] = 0.0f;

    {
        float4 a4 = *(const float4*)(Ab + (size_t)aRow * K + aCol);
        As[0][aCol + 0][aRow] = a4.x;
        As[0][aCol + 1][aRow] = a4.y;
        As[0][aCol + 2][aRow] = a4.z;
        As[0][aCol + 3][aRow] = a4.w;
        float4 b4 = *(const float4*)(Bb + (size_t)bRow * N + bCol);
        *(float4*)&Bs[0][bRow][bCol] = b4;
    }
    __syncthreads();

    int nk = K >> 3;
    for (int t = 0; t < nk; t++) {
        int cur = t & 1;
        float4 a4n, b4n;
        if (t + 1 < nk) {
            int k0 = (t + 1) << 3;
            a4n = *(const float4*)(Ab + (size_t)aRow * K + k0 + aCol);
            b4n = *(const float4*)(Bb + (size_t)(k0 + bRow) * N + bCol);
        }
        #pragma unroll
        for (int kk = 0; kk < 8; kk++) {
            float af[8], bf[8];
            *(float4*)(af)     = *(const float4*)&As[cur][kk][ty * 8];
            *(float4*)(af + 4) = *(const float4*)&As[cur][kk][ty * 8 + 4];
            *(float4*)(bf)     = *(const float4*)&Bs[cur][kk][tx * 8];
            *(float4*)(bf + 4) = *(const float4*)&Bs[cur][kk][tx * 8 + 4];
            #pragma unroll
            for (int m = 0; m < 8; m++)
                #pragma unroll
                for (int n = 0; n < 8; n++)
                    acc[m][n] = fmaf(af[m], bf[n], acc[m][n]);
        }
        if (t + 1 < nk) {
            int nxt = cur ^ 1;
            As[nxt][aCol + 0][aRow] = a4n.x;
            As[nxt][aCol + 1][aRow] = a4n.y;
            As[nxt][aCol + 2][aRow] = a4n.z;
            As[nxt][aCol + 3][aRow] = a4n.w;
            *(float4*)&Bs[nxt][bRow][bCol] = b4n;
        }
        __syncthreads();
    }

    #pragma unroll
    for (int m = 0; m < 8; m++) {
        int row = by * 128 + ty * 8 + m;
        #pragma unroll
        for (int n4 = 0; n4 < 8; n4 += 4) {
            int col = bx * 128 + tx * 8 + n4;
            float4 v;
            v.x = gelu_erf(acc[m][n4 + 0] + bias[col + 0]);
            v.y = gelu_erf(acc[m][n4 + 1] + bias[col + 1]);
            v.z = gelu_erf(acc[m][n4 + 2] + bias[col + 2]);
            v.w = gelu_erf(acc[m][n4 + 3] + bias[col + 3]);
            *(float4*)(C + (size_t)row * N + col) = v;
        }
    }
}

__global__ void k_imp_gemm(const float* __restrict__ x,
                           const float* __restrict__ w1,
                           const float* __restrict__ b1) {
    sgemm_body(x, w1, b1, g_h, ROWS, HID, DIM);
}

// ================== bf16-split tensor-core GEMM (merger MLP) =================
// C = (Ah+Al) @ (Bh+Bl)^T via 3 products (drop Al*Bl), fp32 accum.
// A: [M][K] row-major hi/lo bf16. B: transposed weights [N][K] hi/lo bf16.
// mode 0: v = gelu(acc+bias) -> split-write outH/outL [row][2048]
// mode 1: v = acc+bias -> outF[((row>>7)*384 + (row&127))*2048 + col]

#define CP16(d, p) asm volatile("cp.async.ca.shared.global [%0], [%1], 16;\n" :: "r"(d), "l"(p))
#define CP_COMMIT  asm volatile("cp.async.commit_group;\n")
#define CP_WAIT1   asm volatile("cp.async.wait_group 1;\n" ::: "memory")
#define CP_WAIT0   asm volatile("cp.async.wait_group 0;\n" ::: "memory")

__device__ __forceinline__ void mma16816(float c[4], const unsigned a[4], const unsigned b[2]) {
    asm volatile(
        "mma.sync.aligned.m16n8k16.row.col.f32.bf16.bf16.f32 "
        "{%0,%1,%2,%3}, {%4,%5,%6,%7}, {%8,%9}, {%0,%1,%2,%3};\n"
        : "+f"(c[0]), "+f"(c[1]), "+f"(c[2]), "+f"(c[3])
        : "r"(a[0]), "r"(a[1]), "r"(a[2]), "r"(a[3]), "r"(b[0]), "r"(b[1]));
}

__device__ __forceinline__ void ldsm_x4(unsigned r[4], unsigned addr) {
    asm volatile("ldmatrix.sync.aligned.m8n8.x4.shared.b16 {%0,%1,%2,%3}, [%4];\n"
                 : "=r"(r[0]), "=r"(r[1]), "=r"(r[2]), "=r"(r[3]) : "r"(addr));
}

#define SMPAD 24  /* bf16 elems per row (16 data + 8 pad); 48B row stride, conflict-free */
#define ROWB  (SMPAD * 2)   /* 48 bytes */

__device__ __forceinline__ void mma_gemm_body(
    const __nv_bfloat16* __restrict__ Ah, const __nv_bfloat16* __restrict__ Al,
    const __nv_bfloat16* __restrict__ Bh, const __nv_bfloat16* __restrict__ Bl,
    const float* __restrict__ bias, int K, int mode,
    __nv_bfloat16* __restrict__ outH, __nv_bfloat16* __restrict__ outL,
    float* __restrict__ outF)
{
    // smem: [stage][mat: Ah,Al,Bh,Bl][128 rows * SMPAD] = 2*4*128*24*2B = 48KB
    __shared__ __align__(16) __nv_bfloat16 sm[2][4][128 * SMPAD];
    int tid = threadIdx.x, lane = tid & 31, wid = tid >> 5;
    int wm = wid & 1, wn = wid >> 1;              // warp tile 64x32 in 2x4 grid
    int bm = blockIdx.y, bn = blockIdx.x;

    float acc[4][4][4];
    #pragma unroll
    for (int m = 0; m < 4; m++)
        #pragma unroll
        for (int n = 0; n < 4; n++)
            #pragma unroll
            for (int r = 0; r < 4; r++) acc[m][n][r] = 0.0f;

    // cp.async mapping: 256 threads; r=tid&127 row, half: 0->A mats, 1->B mats
    int r = tid & 127, half = tid >> 7;
    const __nv_bfloat16* gh;
    const __nv_bfloat16* gl;
    if (half == 0) { gh = Ah + (size_t)(bm * 128 + r) * K; gl = Al + (size_t)(bm * 128 + r) * K; }
    else           { gh = Bh + (size_t)(bn * 128 + r) * K; gl = Bl + (size_t)(bn * 128 + r) * K; }
    unsigned smbase = (unsigned)__cvta_generic_to_shared(&sm[0][0][0]);
    const unsigned matStride = 128 * ROWB;           // bytes per matrix slot
    const unsigned stageStride = 4 * matStride;      // bytes per stage
    unsigned sbH0 = smbase + (half * 2    ) * matStride + r * ROWB;
    unsigned sbL0 = smbase + (half * 2 + 1) * matStride + r * ROWB;

    // ldmatrix per-thread address offsets (within a matrix slot)
    // A x4: mats = (rows 0-7,k0-7)(rows 8-15,k0-7)(rows 0-7,k8-15)(rows 8-15,k8-15)
    unsigned aoff = (unsigned)(((lane & 7) + ((lane >> 3) & 1) * 8) * ROWB + (lane >> 4) * 16);
    // B x4: mats = (n 0-7,k0-7)(n 0-7,k8-15)(n 8-15,k0-7)(n 8-15,k8-15)
    //   -> regs map to fb[nt][0], fb[nt][1], fb[nt+1][0], fb[nt+1][1]
    unsigned boff = (unsigned)(((lane & 7) + (lane >> 4) * 8) * ROWB + ((lane >> 3) & 1) * 16);

    int nk = K >> 4;
    // prologue: stage 0
    {
        CP16(sbH0,      gh);  CP16(sbH0 + 16, gh + 8);
        CP16(sbL0,      gl);  CP16(sbL0 + 16, gl + 8);
        CP_COMMIT;
    }
    for (int t = 0; t < nk; t++) {
        if (t + 1 < nk) {
            int k0 = (t + 1) << 4;
            unsigned off = ((t + 1) & 1) ? stageStride : 0;
            CP16(sbH0 + off,      gh + k0);  CP16(sbH0 + off + 16, gh + k0 + 8);
            CP16(sbL0 + off,      gl + k0);  CP16(sbL0 + off + 16, gl + k0 + 8);
            CP_COMMIT;
            CP_WAIT1;
        } else {
            CP_WAIT0;
        }
        __syncthreads();
        unsigned sb = smbase + ((t & 1) ? stageStride : 0);
        unsigned bAh = sb;
        unsigned bAl = sb + matStride;
        unsigned bBh = sb + 2 * matStride;
        unsigned bBl = sb + 3 * matStride;

        // B fragments: 4 nt tiles per h/l, two x4 loads each (nt pairs)
        unsigned fbh[4][2], fbl[4][2];
        #pragma unroll
        for (int np = 0; np < 2; np++) {
            unsigned rb[4];
            ldsm_x4(rb, bBh + (unsigned)((wn * 32 + np * 16) * ROWB) + boff);
            fbh[np * 2][0] = rb[0]; fbh[np * 2][1] = rb[1];
            fbh[np * 2 + 1][0] = rb[2]; fbh[np * 2 + 1][1] = rb[3];
            ldsm_x4(rb, bBl + (unsigned)((wn * 32 + np * 16) * ROWB) + boff);
            fbl[np * 2][0] = rb[0]; fbl[np * 2][1] = rb[1];
            fbl[np * 2 + 1][0] = rb[2]; fbl[np * 2 + 1][1] = rb[3];
        }
        // A fragments loaded per-mt (keeps register count <=128 for 2 CTAs/SM)
        #pragma unroll
        for (int mt = 0; mt < 4; mt++) {
            unsigned fah[4], fal[4];
            unsigned arow = (unsigned)((wm * 64 + mt * 16) * ROWB) + aoff;
            ldsm_x4(fah, bAh + arow);
            ldsm_x4(fal, bAl + arow);
            #pragma unroll
            for (int nt = 0; nt < 4; nt++) {
                mma16816(acc[mt][nt], fah, fbh[nt]);
                mma16816(acc[mt][nt], fah, fbl[nt]);
                mma16816(acc[mt][nt], fal, fbh[nt]);
            }
        }
        __syncthreads();
    }

    // epilogue: c0:(g, 2tg) c1:(g, 2tg+1) c2:(g+8, 2tg) c3:(g+8, 2tg+1)
    int g = lane >> 2, tg = (lane & 3) * 2;
    #pragma unroll
    for (int mt = 0; mt < 4; mt++) {
        #pragma unroll
        for (int nt = 0; nt < 4; nt++) {
            int col = bn * 128 + wn * 32 + nt * 8 + tg;
            float bx0 = bias[col], bx1 = bias[col + 1];
            #pragma unroll
            for (int h = 0; h < 2; h++) {
                int row = bm * 128 + wm * 64 + mt * 16 + g + 8 * h;
                float v0 = acc[mt][nt][2 * h]     + bx0;
                float v1 = acc[mt][nt][2 * h + 1] + bx1;
                if (mode == 0) {
                    v0 = gelu_erf(v0); v1 = gelu_erf(v1);
                    __nv_bfloat16 h0 = __float2bfloat16(v0);
                    __nv_bfloat16 h1 = __float2bfloat16(v1);
                    size_t o = (size_t)row * DIM + col;
                    outH[o]     = h0; outL[o]     = __float2bfloat16(v0 - __bfloat162float(h0));
                    outH[o + 1] = h1; outL[o + 1] = __float2bfloat16(v1 - __bfloat162float(h1));
                } else {
                    int orow = (row >> 7) * 384 + (row & 127);
                    size_t o = (size_t)orow * DIM + col;
                    outF[o] = v0; outF[o + 1] = v1;
                }
            }
        }
    }
}

__global__ void __launch_bounds__(256, 2) k_mma_mrg1(const float* __restrict__ b1) {
    mma_gemm_body(g_pair_h, g_pair_l, g_w1t_h, g_w1t_l, b1, 2 * DIM, 0,
                  g_hid_h, g_hid_l, (float*)0);
}
__global__ void __launch_bounds__(256, 2) k_mma_mrg2(const float* __restrict__ b2,
                                                     float* __restrict__ out) {
    mma_gemm_body(g_hid_h, g_hid_l, g_w2t_h, g_w2t_l, b2, DIM, 1,
                  (__nv_bfloat16*)0, (__nv_bfloat16*)0, out);
}

// -------- weight transpose + bf16 hi/lo split:  W[K][N] -> T[N][K] -----------
__device__ __forceinline__ void cvt_wT_body(const float* __restrict__ W,
                                            __nv_bfloat16* __restrict__ Th,
                                            __nv_bfloat16* __restrict__ Tl,
                                            int K, int N) {
    __shared__ float tile[32][33];
    int k0 = blockIdx.y * 32, n0 = blockIdx.x * 32;
    int tx = threadIdx.x, ty = threadIdx.y;   // 32 x 8
    #pragma unroll
    for (int i = ty; i < 32; i += 8)
        tile[i][tx] = W[(size_t)(k0 + i) * N + n0 + tx];
    __syncthreads();
    #pragma unroll
    for (int i = ty; i < 32; i += 8) {
        float v = tile[tx][i];   // = W[k0+tx][n0+i]
        __nv_bfloat16 h = __float2bfloat16(v);
        size_t o = (size_t)(n0 + i) * K + k0 + tx;
        Th[o] = h;
        Tl[o] = __float2bfloat16(v - __bfloat162float(h));
    }
}
__global__ void k_cvt_w1t(const float* __restrict__ w1) { cvt_wT_body(w1, g_w1t_h, g_w1t_l, 2 * DIM, DIM); }
__global__ void k_cvt_w2t(const float* __restrict__ w2) { cvt_wT_body(w2, g_w2t_h, g_w2t_l, DIM, DIM); }

// -------- pair gather + bf16 hi/lo split -------------------------------------
__global__ void k_cvt_pair(const float* __restrict__ x) {
    int p = blockIdx.x, b = blockIdx.y;
    int i = g_pi[b * NPAIR + p];
    int j = g_pj[b * NPAIR + p];
    const float* xi = x + ((size_t)b * SEQ + i) * DIM;
    const float* xj = x + ((size_t)b * SEQ + j) * DIM;
    size_t ro = (size_t)(b * NPAIR + p) * 2 * DIM;
    for (int c = threadIdx.x; c < DIM; c += 256) {
        float v = xi[c];
        __nv_bfloat16 h = __float2bfloat16(v);
        g_pair_h[ro + c] = h;
        g_pair_l[ro + c] = __float2bfloat16(v - __bfloat162float(h));
        float w = xj[c];
        __nv_bfloat16 h2 = __float2bfloat16(w);
        g_pair_h[ro + DIM + c] = h2;
        g_pair_l[ro + DIM + c] = __float2bfloat16(w - __bfloat162float(h2));
    }
}

// ---------------- importance GEMV + sigmoid (one warp per row) ---------------
__global__ void k_imp(const float* __restrict__ w2, const float* __restrict__ b2) {
    int r = blockIdx.x * 8 + (threadIdx.x >> 5);
    int lane = threadIdx.x & 31;
    const float* hr = g_h + (size_t)r * HID;
    float s = 0.0f;
    for (int c = lane; c < HID; c += 32) s = fmaf(hr[c], w2[c], s);
    #pragma unroll
    for (int o = 16; o; o >>= 1) s += __shfl_down_sync(0xffffffffu, s, o);
    if (lane == 0) {
        float v = s + b2[0];
        g_imp[r] = 1.0f / (1.0f + expf(-v));
    }
}

// ---------------- per-batch min/max normalization + floor --------------------
__global__ void k_norm_imp() {
    int b = blockIdx.x;
    int tid = threadIdx.x;        // 512
    int warp = tid >> 5, lane = tid & 31;
    __shared__ float smn[16], smx[16];
    __shared__ float bmn, bmx;
    float v = g_imp[b * SEQ + tid];
    float mn = v, mx = v;
    #pragma unroll
    for (int o = 16; o; o >>= 1) {
        mn = fminf(mn, __shfl_down_sync(0xffffffffu, mn, o));
        mx = fmaxf(mx, __shfl_down_sync(0xffffffffu, mx, o));
    }
    if (lane == 0) { smn[warp] = mn; smx[warp] = mx; }
    __syncthreads();
    if (warp == 0) {
        float a = (lane < 16) ? smn[lane] : 3.402823466e+38f;
        float c = (lane < 16) ? smx[lane] : NEG_INF;
        #pragma unroll
        for (int o = 8; o; o >>= 1) {
            a = fminf(a, __shfl_down_sync(0xffffffffu, a, o));
            c = fmaxf(c, __shfl_down_sync(0xffffffffu, c, o));
        }
        if (lane == 0) { bmn = a; bmx = c; }
    }
    __syncthreads();
    float mn0 = bmn, mx0 = bmx;
    float nv = (mx0 > mn0) ? (v - mn0) / (mx0 - mn0) : v;
    g_w[b * SEQ + tid] = fmaxf(nv, 0.1f);
}

// ---------------- token L2-normalize -----------------------------------------
__global__ void k_xnorm(const float* __restrict__ x) {
    int tk = blockIdx.x;
    const float4* xr = (const float4*)(x + (size_t)tk * DIM);
    float4* o = (float4*)(g_xn + (size_t)tk * DIM);
    int tid = threadIdx.x;        // 256
    int warp = tid >> 5, lane = tid & 31;
    float ss = 0.0f;
    #pragma unroll
    for (int c = tid; c < DIM / 4; c += 256) {
        float4 v = xr[c];
        ss += v.x * v.x + v.y * v.y + v.z * v.z + v.w * v.w;
    }
    __shared__ float sp[8];
    __shared__ float sden;
    #pragma unroll
    for (int off = 16; off; off >>= 1) ss += __shfl_down_sync(0xffffffffu, ss, off);
    if (lane == 0) sp[warp] = ss;
    __syncthreads();
    if (tid == 0) {
        float t = 0.0f;
        #pragma unroll
        for (int i = 0; i < 8; i++) t += sp[i];
        sden = fmaxf(sqrtf(t), 1e-12f);
    }
    __syncthreads();
    float d = sden;
    #pragma unroll
    for (int c = tid; c < DIM / 4; c += 256) {
        float4 v = xr[c];
        v.x /= d; v.y /= d; v.z /= d; v.w /= d;
        o[c] = v;
    }
}

// ------- similarity GEMM (xn @ xn^T), double-buffered, + score epilogue ------
// A and B tiles use identical load/compute code with commuted operands, so
// score[i][j] and score[j][i] are bitwise equal (selection tie-break relies on it).
__global__ void k_sim() {
    int b = blockIdx.z;
    const float* Xb = g_xn + (size_t)b * SEQ * DIM;
    float* Sc = g_score + (size_t)b * SEQ * SEQ;
    const float* Wb = g_w + b * SEQ;

    __shared__ float As[2][8][128];
    __shared__ float Bs[2][8][128];
    int tid = threadIdx.x;
    int bx = blockIdx.x, by = blockIdx.y;
    const float* Ab = Xb + (size_t)(by * 128) * DIM;
    const float* Bb = Xb + (size_t)(bx * 128) * DIM;
    int aRow = tid >> 1, aCol = (tid & 1) * 4;
    int ty = tid >> 4, tx = tid & 15;
    float acc[8][8];
    #pragma unroll
    for (int m = 0; m < 8; m++)
        #pragma unroll
        for (int n = 0; n < 8; n++) acc[m][n] = 0.0f;

    {
        float4 a4 = *(const float4*)(Ab + (size_t)aRow * DIM + aCol);
        As[0][aCol + 0][aRow] = a4.x;
        As[0][aCol + 1][aRow] = a4.y;
        As[0][aCol + 2][aRow] = a4.z;
        As[0][aCol + 3][aRow] = a4.w;
        float4 b4 = *(const float4*)(Bb + (size_t)aRow * DIM + aCol);
        Bs[0][aCol + 0][aRow] = b4.x;
        Bs[0][aCol + 1][aRow] = b4.y;
        Bs[0][aCol + 2][aRow] = b4.z;
        Bs[0][aCol + 3][aRow] = b4.w;
    }
    __syncthreads();

    const int nk = DIM >> 3;
    for (int t = 0; t < nk; t++) {
        int cur = t & 1;
        float4 a4n, b4n;
        if (t + 1 < nk) {
            int k0 = (t + 1) << 3;
            a4n = *(const float4*)(Ab + (size_t)aRow * DIM + k0 + aCol);
            b4n = *(const float4*)(Bb + (size_t)aRow * DIM + k0 + aCol);
        }
        #pragma unroll
        for (int kk = 0; kk < 8; kk++) {
            float af[8], bf[8];
            *(float4*)(af)     = *(const float4*)&As[cur][kk][ty * 8];
            *(float4*)(af + 4) = *(const float4*)&As[cur][kk][ty * 8 + 4];
            *(float4*)(bf)     = *(const float4*)&Bs[cur][kk][tx * 8];
            *(float4*)(bf + 4) = *(const float4*)&Bs[cur][kk][tx * 8 + 4];
            #pragma unroll
            for (int m = 0; m < 8; m++)
                #pragma unroll
                for (int n = 0; n < 8; n++)
                    acc[m][n] = fmaf(af[m], bf[n], acc[m][n]);
        }
        if (t + 1 < nk) {
            int nxt = cur ^ 1;
            As[nxt][aCol + 0][aRow] = a4n.x;
            As[nxt][aCol + 1][aRow] = a4n.y;
            As[nxt][aCol + 2][aRow] = a4n.z;
            As[nxt][aCol + 3][aRow] = a4n.w;
            Bs[nxt][aCol + 0][aRow] = b4n.x;
            Bs[nxt][aCol + 1][aRow] = b4n.y;
            Bs[nxt][aCol + 2][aRow] = b4n.z;
            Bs[nxt][aCol + 3][aRow] = b4n.w;
        }
        __syncthreads();
    }

    #pragma unroll
    for (int m = 0; m < 8; m++) {
        int i = by * 128 + ty * 8 + m;
        float wi = Wb[i];
        #pragma unroll
        for (int n4 = 0; n4 < 8; n4 += 4) {
            int j = bx * 128 + tx * 8 + n4;
            float4 v;
            v.x = (i == j + 0) ? -1.0f : acc[m][n4 + 0] / (wi * Wb[j + 0]);
            v.y = (i == j + 1) ? -1.0f : acc[m][n4 + 1] / (wi * Wb[j + 1]);
            v.z = (i == j + 2) ? -1.0f : acc[m][n4 + 2] / (wi * Wb[j + 2]);
            v.w = (i == j + 3) ? -1.0f : acc[m][n4 + 3] / (wi * Wb[j + 3]);
            *(float4*)(Sc + (size_t)i * SEQ + j) = v;
        }
    }
}

// ---------------- greedy pair selection (one CTA per batch) ------------------
__global__ void __launch_bounds__(512) k_greedy() {
    int b = blockIdx.x;
    const float* Sm = g_score + (size_t)b * SEQ * SEQ;
    __shared__ float rmax[SEQ];
    __shared__ int   rarg[SEQ];
    __shared__ int   avail[SEQ];
    __shared__ float pv[16];
    __shared__ int   pidx[16];
    __shared__ int   list[SEQ];
    __shared__ int   listn;
    __shared__ int   s_i, s_j;
    int tid = threadIdx.x, warp = tid >> 5, lane = tid & 31;
    avail[tid] = 1;
    __syncthreads();

    for (int r = warp; r < SEQ; r += 16) {
        float best = NEG_INF; int bj = 0;
        for (int c = lane; c < SEQ; c += 32) {
            float v = Sm[r * SEQ + c];
            if (v > best) { best = v; bj = c; }
        }
        #pragma unroll
        for (int o = 16; o; o >>= 1) {
            float ov = __shfl_down_sync(0xffffffffu, best, o);
            int   oj = __shfl_down_sync(0xffffffffu, bj, o);
            if (ov > best || (ov == best && oj < bj)) { best = ov; bj = oj; }
        }
        if (lane == 0) { rmax[r] = best; rarg[r] = bj; }
    }
    __syncthreads();

    for (int t = 0; t < NPAIR; t++) {
        float v = avail[tid] ? rmax[tid] : NEG_INF;
        int ridx = tid;
        #pragma unroll
        for (int o = 16; o; o >>= 1) {
            float ov = __shfl_down_sync(0xffffffffu, v, o);
            int   oi = __shfl_down_sync(0xffffffffu, ridx, o);
            if (ov > v || (ov == v && oi < ridx)) { v = ov; ridx = oi; }
        }
        if (lane == 0) { pv[warp] = v; pidx[warp] = ridx; }
        __syncthreads();
        if (warp == 0) {
            float v2 = (lane < 16) ? pv[lane] : NEG_INF;
            int   i2 = (lane < 16) ? pidx[lane] : 0x7fffffff;
            #pragma unroll
            for (int o = 8; o; o >>= 1) {
                float ov = __shfl_down_sync(0xffffffffu, v2, o);
                int   oi = __shfl_down_sync(0xffffffffu, i2, o);
                if (ov > v2 || (ov == v2 && oi < i2)) { v2 = ov; i2 = oi; }
            }
            if (lane == 0) {
                int i = i2, j = rarg[i2];
                s_i = i; s_j = j;
                g_pi[b * NPAIR + t] = i;
                g_pj[b * NPAIR + t] = j;
                avail[i] = 0; avail[j] = 0;
                listn = 0;
            }
        }
        __syncthreads();
        int i = s_i, j = s_j;
        if (avail[tid] && (rarg[tid] == i || rarg[tid] == j)) {
            int p = atomicAdd(&listn, 1);
            list[p] = tid;
        }
        __syncthreads();
        int n = listn;
        for (int li = warp; li < n; li += 16) {
            int r = list[li];
            float best = NEG_INF; int bj = 0;
            for (int c = lane; c < SEQ; c += 32) {
                if (avail[c]) {
                    float vv = Sm[r * SEQ + c];
                    if (vv > best) { best = vv; bj = c; }
                }
            }
            #pragma unroll
            for (int o = 16; o; o >>= 1) {
                float ov = __shfl_down_sync(0xffffffffu, best, o);
                int   oj = __shfl_down_sync(0xffffffffu, bj, o);
                if (ov > best || (ov == best && oj < bj)) { best = ov; bj = oj; }
            }
            if (lane == 0) { rmax[r] = best; rarg[r] = bj; }
        }
        __syncthreads();
    }

    if (tid == 0) {
        int c = 0;
        for (int s2 = 0; s2 < SEQ; s2++)
            if (avail[s2]) g_un[b * NUN + c++] = s2;
    }
}

// ---------------- unmerged gather --------------------------------------------
__global__ void k_gather_un(const float* __restrict__ x, float* __restrict__ out) {
    int u = blockIdx.x, b = blockIdx.y;
    int idx = g_un[b * NUN + u];
    const float4* src = (const float4*)(x + ((size_t)b * SEQ + idx) * DIM);
    float4* dst = (float4*)(out + ((size_t)(b * 384 + NPAIR + u)) * DIM);
    int tid = threadIdx.x;
    #pragma unroll
    for (int c = tid; c < DIM / 4; c += 256) dst[c] = src[c];
}

// ---------------- launch -----------------------------------------------------
extern "C" void kernel_launch(void* const* d_in, const int* in_sizes, int n_in,
                              void* d_out, int out_size) {
    const float* x      = (const float*)d_in[0];
    const float* imp_w1 = (const float*)d_in[1];
    const float* imp_b1 = (const float*)d_in[2];
    const float* imp_w2 = (const float*)d_in[3];
    const float* imp_b2 = (const float*)d_in[4];
    const float* mrg_w1 = (const float*)d_in[5];
    const float* mrg_b1 = (const float*)d_in[6];
    const float* mrg_w2 = (const float*)d_in[7];
    const float* mrg_b2 = (const float*)d_in[8];
    float* out = (float*)d_out;

    // weight transpose+split (independent of data path)
    k_cvt_w1t<<<dim3(DIM / 32, 2 * DIM / 32), dim3(32, 8)>>>(mrg_w1);
    k_cvt_w2t<<<dim3(DIM / 32, DIM / 32), dim3(32, 8)>>>(mrg_w2);

    // importance MLP (fp32 exact — feeds selection)
    k_imp_gemm<<<dim3(HID / 128, ROWS / 128), 256>>>(x, imp_w1, imp_b1);
    k_imp<<<ROWS / 8, 256>>>(imp_w2, imp_b2);
    k_norm_imp<<<BATCH, SEQ>>>();
    k_xnorm<<<ROWS, 256>>>(x);
    k_sim<<<dim3(SEQ / 128, SEQ / 128, BATCH), 256>>>();
    k_greedy<<<BATCH, SEQ>>>();

    // gathers
    k_cvt_pair<<<dim3(NPAIR, BATCH), 256>>>(x);
    k_gather_un<<<dim3(NUN, BATCH), 256>>>(x, out);

    // merger MLP on tensor cores (bf16-split, fp32 accum)
    k_mma_mrg1<<<dim3(DIM / 128, MROWS / 128), 256>>>(mrg_b1);
    k_mma_mrg2<<<dim3(DIM / 128, MROWS / 128), 256>>>(mrg_b2, out);

    (void)in_sizes; (void)n_in; (void)out_size;
}